// round 1
// baseline (speedup 1.0000x reference)
#include <cuda_runtime.h>
#include <cuda_bf16.h>
#include <cstddef>

#define BT      64      // chunk size
#define DIM     128     // head dim (key & value)
#define NC      64      // number of chunks
#define SEQ     4096
#define EB      32      // value-dim block per CTA
#define NEB     4       // DIM / EB
#define NTHREADS 256

// SMEM float counts
#define SQT_SZ  (DIM*BT)     // 8192  sqT[d][i]
#define SKT_SZ  (DIM*BT)     // 8192  skT[d][i]
#define SV_SZ   (BT*EB)      // 2048  sv[i][e]
#define SA_SZ   (BT*BT)      // 4096  sA[i][j]
#define ST_SZ   (DIM*EB)     // 4096  state[d][e]

__global__ __launch_bounds__(NTHREADS, 1)
void gdelta_kernel(const float* __restrict__ q,
                   const float* __restrict__ k,
                   const float* __restrict__ v,
                   const float* __restrict__ beta,
                   float* __restrict__ out)
{
    extern __shared__ float sm[];
    float* sqT   = sm;                    // [DIM][BT]
    float* skT   = sqT + SQT_SZ;          // [DIM][BT]
    float* sv    = skT + SKT_SZ;          // [BT][EB]
    float* sA    = sv  + SV_SZ;           // [BT][BT]
    float* st    = sA  + SA_SZ;           // [DIM][EB]
    float* cum   = st  + ST_SZ;           // [BT]
    float* dfs   = cum + BT;              // [BT]
    float* dte   = dfs + BT;              // [BT]
    float* setot = dte + BT;              // [1]

    const int t    = threadIdx.x;
    const int lane = t & 31;
    const int warp = t >> 5;
    const int bh   = blockIdx.y;
    const int eb   = blockIdx.x;

    const size_t base = (size_t)bh * SEQ * DIM;
    const float* qb = q + base;
    const float* kb = k + base;
    const float* vb = v + base + (size_t)eb * EB;
    const float* betab = beta + (size_t)bh * SEQ;
    float* ob = out + base + (size_t)eb * EB;

    // zero state
    for (int i = t; i < ST_SZ; i += NTHREADS) st[i] = 0.0f;

    for (int c = 0; c < NC; ++c) {
        __syncthreads();   // protects sqT/skT/sv reuse (prev chunk step6) + state init

        // ---------- beta log-cumsum (warp 0) ----------
        if (warp == 0) {
            float b0 = logf(betab[c*BT + lane]      + 1e-6f);
            float b1 = logf(betab[c*BT + 32 + lane] + 1e-6f);
            #pragma unroll
            for (int off = 1; off < 32; off <<= 1) {
                float n = __shfl_up_sync(0xffffffffu, b0, off);
                if (lane >= off) b0 += n;
            }
            float t0 = __shfl_sync(0xffffffffu, b0, 31);
            #pragma unroll
            for (int off = 1; off < 32; off <<= 1) {
                float n = __shfl_up_sync(0xffffffffu, b1, off);
                if (lane >= off) b1 += n;
            }
            float c1  = t0 + b1;
            float tot = __shfl_sync(0xffffffffu, c1, 31);
            cum[lane]      = b0;
            cum[32 + lane] = c1;
            dfs[lane]      = __expf(b0);
            dfs[32 + lane] = __expf(c1);
            dte[lane]      = __expf(tot - b0);
            dte[32 + lane] = __expf(tot - c1);
            if (lane == 0) setot[0] = __expf(tot);
        }

        // ---------- load q,k transposed; v direct ----------
        {
            const float* qrow = qb + (size_t)c * BT * DIM;
            const float* krow = kb + (size_t)c * BT * DIM;
            #pragma unroll
            for (int it = 0; it < 8; ++it) {
                int p  = t + it * NTHREADS;      // 0..2047
                int i  = p & 63;
                int d4 = p >> 6;                 // 0..31
                float4 vq = *(const float4*)(qrow + (size_t)i * DIM + d4 * 4);
                sqT[(4*d4 + 0)*BT + i] = vq.x;
                sqT[(4*d4 + 1)*BT + i] = vq.y;
                sqT[(4*d4 + 2)*BT + i] = vq.z;
                sqT[(4*d4 + 3)*BT + i] = vq.w;
                float4 vk = *(const float4*)(krow + (size_t)i * DIM + d4 * 4);
                skT[(4*d4 + 0)*BT + i] = vk.x;
                skT[(4*d4 + 1)*BT + i] = vk.y;
                skT[(4*d4 + 2)*BT + i] = vk.z;
                skT[(4*d4 + 3)*BT + i] = vk.w;
            }
            const float* vrow = vb + (size_t)c * BT * DIM;
            #pragma unroll
            for (int it = 0; it < 2; ++it) {
                int p  = t + it * NTHREADS;      // 0..511
                int e4 = p & 7;
                int i  = p >> 3;
                float4 vv = *(const float4*)(vrow + (size_t)i * DIM + 4 * e4);
                *(float4*)(sv + i * EB + 4 * e4) = vv;
            }
        }
        __syncthreads();

        // ---------- step 3: A[i][j] = (q_i . k_j) * exp(cum_i - cum_j), j<=i ----------
        {
            const int tx = t & 15;      // j tile
            const int ty = t >> 4;      // i tile
            float acc[4][4];
            #pragma unroll
            for (int r = 0; r < 4; ++r)
                #pragma unroll
                for (int cc = 0; cc < 4; ++cc) acc[r][cc] = 0.0f;

            #pragma unroll 4
            for (int d = 0; d < DIM; ++d) {
                float4 a = *(const float4*)(sqT + d*BT + 4*ty);
                float4 b = *(const float4*)(skT + d*BT + 4*tx);
                acc[0][0] += a.x*b.x; acc[0][1] += a.x*b.y; acc[0][2] += a.x*b.z; acc[0][3] += a.x*b.w;
                acc[1][0] += a.y*b.x; acc[1][1] += a.y*b.y; acc[1][2] += a.y*b.z; acc[1][3] += a.y*b.w;
                acc[2][0] += a.z*b.x; acc[2][1] += a.z*b.y; acc[2][2] += a.z*b.z; acc[2][3] += a.z*b.w;
                acc[3][0] += a.w*b.x; acc[3][1] += a.w*b.y; acc[3][2] += a.w*b.z; acc[3][3] += a.w*b.w;
            }
            float ci[4], cj[4];
            #pragma unroll
            for (int r = 0; r < 4; ++r) ci[r] = cum[4*ty + r];
            #pragma unroll
            for (int cc = 0; cc < 4; ++cc) cj[cc] = cum[4*tx + cc];
            #pragma unroll
            for (int r = 0; r < 4; ++r) {
                const int i = 4*ty + r;
                float4 row;
                float vals[4];
                #pragma unroll
                for (int cc = 0; cc < 4; ++cc) {
                    const int j = 4*tx + cc;
                    vals[cc] = (j <= i) ? acc[r][cc] * __expf(ci[r] - cj[cc]) : 0.0f;
                }
                row.x = vals[0]; row.y = vals[1]; row.z = vals[2]; row.w = vals[3];
                *(float4*)(sA + i*BT + 4*tx) = row;
            }
        }
        __syncthreads();

        // ---------- step 4+5: out = A @ v  +  dfs * (q @ state) ----------
        {
            const int e  = t & 31;
            const int i0 = (t >> 5) * 8;
            float o[8];
            #pragma unroll
            for (int r = 0; r < 8; ++r) o[r] = 0.0f;

            // inter-chunk: q @ state (old state)
            #pragma unroll 4
            for (int d = 0; d < DIM; ++d) {
                float s = st[d*EB + e];
                float4 qa = *(const float4*)(sqT + d*BT + i0);
                float4 qc = *(const float4*)(sqT + d*BT + i0 + 4);
                o[0] += qa.x * s; o[1] += qa.y * s; o[2] += qa.z * s; o[3] += qa.w * s;
                o[4] += qc.x * s; o[5] += qc.y * s; o[6] += qc.z * s; o[7] += qc.w * s;
            }
            #pragma unroll
            for (int r = 0; r < 8; ++r) o[r] *= dfs[i0 + r];

            // intra-chunk: A @ v, causal => j <= i0+7 (warp-uniform bound)
            const int nj4 = (i0 >> 2) + 2;
            for (int j4 = 0; j4 < nj4; ++j4) {
                float v0 = sv[(4*j4 + 0)*EB + e];
                float v1 = sv[(4*j4 + 1)*EB + e];
                float v2 = sv[(4*j4 + 2)*EB + e];
                float v3 = sv[(4*j4 + 3)*EB + e];
                #pragma unroll
                for (int r = 0; r < 8; ++r) {
                    float4 a = *(const float4*)(sA + (i0 + r)*BT + 4*j4);
                    o[r] += a.x*v0 + a.y*v1 + a.z*v2 + a.w*v3;
                }
            }
            float* orow = ob + (size_t)(c*BT + i0) * DIM;
            #pragma unroll
            for (int r = 0; r < 8; ++r) orow[(size_t)r * DIM + e] = o[r];
        }
        __syncthreads();   // all state reads done before update

        // ---------- step 6: state = state*exp(tot) + (k*dte)^T @ v ----------
        {
            const int e  = t & 31;
            const int d0 = (t >> 5) * 16;
            float acc[16];
            #pragma unroll
            for (int r = 0; r < 16; ++r) acc[r] = 0.0f;

            for (int j4 = 0; j4 < 16; ++j4) {
                float v0 = sv[(4*j4 + 0)*EB + e] * dte[4*j4 + 0];
                float v1 = sv[(4*j4 + 1)*EB + e] * dte[4*j4 + 1];
                float v2 = sv[(4*j4 + 2)*EB + e] * dte[4*j4 + 2];
                float v3 = sv[(4*j4 + 3)*EB + e] * dte[4*j4 + 3];
                #pragma unroll
                for (int r = 0; r < 16; ++r) {
                    float4 kk = *(const float4*)(skT + (d0 + r)*BT + 4*j4);
                    acc[r] += kk.x*v0 + kk.y*v1 + kk.z*v2 + kk.w*v3;
                }
            }
            float et = setot[0];
            #pragma unroll
            for (int r = 0; r < 16; ++r) {
                int d = d0 + r;
                st[d*EB + e] = st[d*EB + e] * et + acc[r];
            }
        }
    }
}

extern "C" void kernel_launch(void* const* d_in, const int* in_sizes, int n_in,
                              void* d_out, int out_size)
{
    const float* q    = (const float*)d_in[0];
    const float* k    = (const float*)d_in[1];
    const float* v    = (const float*)d_in[2];
    const float* beta = (const float*)d_in[3];
    float* out = (float*)d_out;

    const int BH = in_sizes[3] / SEQ;   // 32

    const size_t smem = (size_t)(SQT_SZ + SKT_SZ + SV_SZ + SA_SZ + ST_SZ + 3*BT + 32) * sizeof(float);
    cudaFuncSetAttribute(gdelta_kernel, cudaFuncAttributeMaxDynamicSharedMemorySize, (int)smem);

    dim3 grid(NEB, BH);
    gdelta_kernel<<<grid, NTHREADS, smem>>>(q, k, v, beta, out);
}

// round 3
// speedup vs baseline: 1.1691x; 1.1691x over previous
#include <cuda_runtime.h>
#include <cuda_bf16.h>
#include <cstddef>

#define SEQ   4096
#define DIMX  128
#define BT    64
#define NCH   64     // SEQ/BT
#define BHMAX 32

// Scratch (allowed: __device__ globals). 32*64*128*128 floats = 128 MB.
__device__ float g_state[BHMAX * NCH * DIMX * DIMX];
__device__ float g_cum[BHMAX * SEQ];
__device__ float g_tot[BHMAX * NCH];

// ───────────────────────── Pass A: per-chunk update matrices ─────────────────────────
// upd_c[d][e] = sum_j k[j][d] * dte[j] * v[j][e]   (also writes cum/tot to global)
__global__ __launch_bounds__(256, 2)
void pass_upd(const float* __restrict__ k, const float* __restrict__ v,
              const float* __restrict__ beta)
{
    extern __shared__ float sm[];
    float* sk  = sm;           // [64][128]
    float* sve = sk + 8192;    // [64][128]  v * dte[j]
    float* cum = sve + 8192;   // [64]
    float* dte = cum + 64;     // [64]

    const int t = threadIdx.x, lane = t & 31, warp = t >> 5;
    const int c = blockIdx.x, bh = blockIdx.y;
    const float* betab = beta + (size_t)bh * SEQ + c * BT;

    if (warp == 0) {
        float b0 = logf(betab[lane]      + 1e-6f);
        float b1 = logf(betab[32 + lane] + 1e-6f);
        #pragma unroll
        for (int off = 1; off < 32; off <<= 1) {
            float n = __shfl_up_sync(0xffffffffu, b0, off);
            if (lane >= off) b0 += n;
        }
        float t0 = __shfl_sync(0xffffffffu, b0, 31);
        #pragma unroll
        for (int off = 1; off < 32; off <<= 1) {
            float n = __shfl_up_sync(0xffffffffu, b1, off);
            if (lane >= off) b1 += n;
        }
        float c1  = t0 + b1;
        float tot = __shfl_sync(0xffffffffu, c1, 31);
        cum[lane]      = b0;
        cum[32 + lane] = c1;
        dte[lane]      = __expf(tot - b0);
        dte[32 + lane] = __expf(tot - c1);
        g_cum[bh * SEQ + c * BT + lane]      = b0;
        g_cum[bh * SEQ + c * BT + 32 + lane] = c1;
        if (lane == 0) g_tot[bh * NCH + c] = tot;
    }
    __syncthreads();

    const float* kb = k + ((size_t)bh * SEQ + c * BT) * DIMX;
    const float* vb = v + ((size_t)bh * SEQ + c * BT) * DIMX;
    #pragma unroll
    for (int it = 0; it < 8; ++it) {
        int p = t + it * 256;
        int j = p >> 5, f = p & 31;
        float4 kk = *(const float4*)(kb + (size_t)j * DIMX + 4 * f);
        *(float4*)(sk + j * DIMX + 4 * f) = kk;
        float4 vv = *(const float4*)(vb + (size_t)j * DIMX + 4 * f);
        float dd = dte[j];
        vv.x *= dd; vv.y *= dd; vv.z *= dd; vv.w *= dd;
        *(float4*)(sve + j * DIMX + 4 * f) = vv;
    }
    __syncthreads();

    const int te = t & 15, td = t >> 4;
    const int e0 = 8 * te, d0 = 8 * td;
    float acc[8][8];
    #pragma unroll
    for (int r = 0; r < 8; ++r)
        #pragma unroll
        for (int cc = 0; cc < 8; ++cc) acc[r][cc] = 0.0f;

    #pragma unroll 2
    for (int j = 0; j < BT; ++j) {
        float4 ka = *(const float4*)(sk + j * DIMX + d0);
        float4 kc = *(const float4*)(sk + j * DIMX + d0 + 4);
        float4 va = *(const float4*)(sve + j * DIMX + e0);
        float4 vc = *(const float4*)(sve + j * DIMX + e0 + 4);
        float kr[8] = {ka.x, ka.y, ka.z, ka.w, kc.x, kc.y, kc.z, kc.w};
        float vr[8] = {va.x, va.y, va.z, va.w, vc.x, vc.y, vc.z, vc.w};
        #pragma unroll
        for (int r = 0; r < 8; ++r)
            #pragma unroll
            for (int cc = 0; cc < 8; ++cc) acc[r][cc] += kr[r] * vr[cc];
    }

    float* dst = g_state + ((size_t)(bh * NCH + c) << 14);
    #pragma unroll
    for (int r = 0; r < 8; ++r) {
        float4 w0 = {acc[r][0], acc[r][1], acc[r][2], acc[r][3]};
        float4 w1 = {acc[r][4], acc[r][5], acc[r][6], acc[r][7]};
        *(float4*)(dst + (d0 + r) * DIMX + e0)     = w0;
        *(float4*)(dst + (d0 + r) * DIMX + e0 + 4) = w1;
    }
}

// ───────────────────────── Pass B: in-place scan upd → S_before ─────────────────────────
__global__ __launch_bounds__(256)
void pass_scan()
{
    __shared__ float et[NCH];
    const int t = threadIdx.x;
    const int seg = blockIdx.x;     // 0..15
    const int bh  = blockIdx.y;
    if (t < NCH) et[t] = __expf(g_tot[bh * NCH + t]);
    __syncthreads();

    const size_t base = ((size_t)bh * NCH) << 14;
    const int off = seg * 1024 + 4 * t;
    float4 s = {0.f, 0.f, 0.f, 0.f};
    #pragma unroll 2
    for (int c = 0; c < NCH; ++c) {
        float* p = g_state + base + ((size_t)c << 14) + off;
        float4 u = *(const float4*)p;
        *(float4*)p = s;
        float e = et[c];
        s.x = s.x * e + u.x;
        s.y = s.y * e + u.y;
        s.z = s.z * e + u.z;
        s.w = s.w * e + u.w;
    }
}

// ───────────────────────── Pass C: outputs (intra + inter) ─────────────────────────
__global__ __launch_bounds__(512, 1)
void pass_out(const float* __restrict__ q, const float* __restrict__ k,
              const float* __restrict__ v, float* __restrict__ out)
{
    extern __shared__ float sm[];
    float* sqT = sm;            // [128][64]
    float* skT = sqT + 8192;    // [128][64]
    float* sv  = skT + 8192;    // [64][128]
    float* sA  = sv + 8192;     // [64][64]
    float* sS  = sA + 4096;     // [16][128]
    float* cum = sS + 2048;     // [64]
    float* dfs = cum + 64;      // [64]

    const int t = threadIdx.x;
    const int c = blockIdx.x, bh = blockIdx.y;
    const size_t cb = ((size_t)bh * SEQ + (size_t)c * BT) * DIMX;
    const float* qrow = q + cb;
    const float* krow = k + cb;
    const float* vrow = v + cb;

    if (t < 64) {
        float cc = g_cum[bh * SEQ + c * BT + t];
        cum[t] = cc;
        dfs[t] = __expf(cc);
    }
    #pragma unroll
    for (int it = 0; it < 4; ++it) {
        int p  = t + it * 512;              // 0..2047
        int i  = p & 63;
        int d4 = p >> 6;                    // 0..31
        float4 vq = *(const float4*)(qrow + (size_t)i * DIMX + 4 * d4);
        sqT[(4 * d4 + 0) * BT + i] = vq.x;
        sqT[(4 * d4 + 1) * BT + i] = vq.y;
        sqT[(4 * d4 + 2) * BT + i] = vq.z;
        sqT[(4 * d4 + 3) * BT + i] = vq.w;
        float4 vk = *(const float4*)(krow + (size_t)i * DIMX + 4 * d4);
        skT[(4 * d4 + 0) * BT + i] = vk.x;
        skT[(4 * d4 + 1) * BT + i] = vk.y;
        skT[(4 * d4 + 2) * BT + i] = vk.z;
        skT[(4 * d4 + 3) * BT + i] = vk.w;
        int j = p >> 5, f = p & 31;
        float4 vv = *(const float4*)(vrow + (size_t)j * DIMX + 4 * f);
        *(float4*)(sv + j * DIMX + 4 * f) = vv;
    }
    __syncthreads();

    // ── A = (QK^T) ⊙ decay, causal-masked ──
    {
        const int tj = t & 15, ti = t >> 4;       // j0=4*tj, i0=2*ti
        const int i0 = 2 * ti, j0 = 4 * tj;
        float a[2][4];
        #pragma unroll
        for (int r = 0; r < 2; ++r)
            #pragma unroll
            for (int cc = 0; cc < 4; ++cc) a[r][cc] = 0.0f;
        #pragma unroll 4
        for (int d = 0; d < DIMX; ++d) {
            float2 qa = *(const float2*)(sqT + d * BT + i0);
            float4 kb = *(const float4*)(skT + d * BT + j0);
            a[0][0] += qa.x * kb.x; a[0][1] += qa.x * kb.y;
            a[0][2] += qa.x * kb.z; a[0][3] += qa.x * kb.w;
            a[1][0] += qa.y * kb.x; a[1][1] += qa.y * kb.y;
            a[1][2] += qa.y * kb.z; a[1][3] += qa.y * kb.w;
        }
        float cj[4];
        #pragma unroll
        for (int cc = 0; cc < 4; ++cc) cj[cc] = cum[j0 + cc];
        #pragma unroll
        for (int r = 0; r < 2; ++r) {
            int i = i0 + r;
            float ci = cum[i];
            float vals[4];
            #pragma unroll
            for (int cc = 0; cc < 4; ++cc) {
                int j = j0 + cc;
                vals[cc] = (j <= i) ? a[r][cc] * __expf(ci - cj[cc]) : 0.0f;
            }
            float4 row = {vals[0], vals[1], vals[2], vals[3]};
            *(float4*)(sA + i * BT + j0) = row;
        }
    }

    // ── out = A @ v  +  dfs ⊙ (q @ S_before) ──
    const int te = t & 15, ti = t >> 4;
    const int e0 = 8 * te, i0 = 2 * ti;
    float o[2][8];
    #pragma unroll
    for (int r = 0; r < 2; ++r)
        #pragma unroll
        for (int cc = 0; cc < 8; ++cc) o[r][cc] = 0.0f;

    const size_t sbase = ((size_t)(bh * NCH + c)) << 14;
    for (int blk = 0; blk < 8; ++blk) {
        __syncthreads();
        *(float4*)(sS + 4 * t) = *(const float4*)(g_state + sbase + blk * 2048 + 4 * t);
        __syncthreads();
        #pragma unroll 4
        for (int dd = 0; dd < 16; ++dd) {
            int d = blk * 16 + dd;
            float2 qa = *(const float2*)(sqT + d * BT + i0);
            float4 s0 = *(const float4*)(sS + dd * DIMX + e0);
            float4 s1 = *(const float4*)(sS + dd * DIMX + e0 + 4);
            o[0][0] += qa.x * s0.x; o[0][1] += qa.x * s0.y; o[0][2] += qa.x * s0.z; o[0][3] += qa.x * s0.w;
            o[0][4] += qa.x * s1.x; o[0][5] += qa.x * s1.y; o[0][6] += qa.x * s1.z; o[0][7] += qa.x * s1.w;
            o[1][0] += qa.y * s0.x; o[1][1] += qa.y * s0.y; o[1][2] += qa.y * s0.z; o[1][3] += qa.y * s0.w;
            o[1][4] += qa.y * s1.x; o[1][5] += qa.y * s1.y; o[1][6] += qa.y * s1.z; o[1][7] += qa.y * s1.w;
        }
    }
    {
        float f0 = dfs[i0], f1 = dfs[i0 + 1];
        #pragma unroll
        for (int cc = 0; cc < 8; ++cc) { o[0][cc] *= f0; o[1][cc] *= f1; }
    }
    // intra-chunk: causal — warp w needs j ≤ 4w+3 (upper-tri A entries are 0)
    const int w = t >> 5;
    for (int j4 = 0; j4 <= w; ++j4) {
        #pragma unroll
        for (int s = 0; s < 4; ++s) {
            int j = 4 * j4 + s;
            float a0 = sA[i0 * BT + j];
            float a1 = sA[(i0 + 1) * BT + j];
            float4 v0 = *(const float4*)(sv + j * DIMX + e0);
            float4 v1 = *(const float4*)(sv + j * DIMX + e0 + 4);
            o[0][0] += a0 * v0.x; o[0][1] += a0 * v0.y; o[0][2] += a0 * v0.z; o[0][3] += a0 * v0.w;
            o[0][4] += a0 * v1.x; o[0][5] += a0 * v1.y; o[0][6] += a0 * v1.z; o[0][7] += a0 * v1.w;
            o[1][0] += a1 * v0.x; o[1][1] += a1 * v0.y; o[1][2] += a1 * v0.z; o[1][3] += a1 * v0.w;
            o[1][4] += a1 * v1.x; o[1][5] += a1 * v1.y; o[1][6] += a1 * v1.z; o[1][7] += a1 * v1.w;
        }
    }
    float* dst = out + cb;
    #pragma unroll
    for (int r = 0; r < 2; ++r) {
        float4 w0 = {o[r][0], o[r][1], o[r][2], o[r][3]};
        float4 w1 = {o[r][4], o[r][5], o[r][6], o[r][7]};
        *(float4*)(dst + (i0 + r) * DIMX + e0)     = w0;
        *(float4*)(dst + (i0 + r) * DIMX + e0 + 4) = w1;
    }
}

extern "C" void kernel_launch(void* const* d_in, const int* in_sizes, int n_in,
                              void* d_out, int out_size)
{
    const float* q    = (const float*)d_in[0];
    const float* k    = (const float*)d_in[1];
    const float* v    = (const float*)d_in[2];
    const float* beta = (const float*)d_in[3];
    float* out = (float*)d_out;

    const int BH = in_sizes[3] / SEQ;   // 32

    const size_t smemA = (size_t)(8192 * 2 + 128 + 32) * sizeof(float);
    const size_t smemC = (size_t)(8192 * 3 + 4096 + 2048 + 128 + 32) * sizeof(float);
    cudaFuncSetAttribute(pass_upd, cudaFuncAttributeMaxDynamicSharedMemorySize, (int)smemA);
    cudaFuncSetAttribute(pass_out, cudaFuncAttributeMaxDynamicSharedMemorySize, (int)smemC);

    dim3 gA(NCH, BH);
    pass_upd<<<gA, 256, smemA>>>(k, v, beta);

    dim3 gB(16, BH);
    pass_scan<<<gB, 256>>>();

    dim3 gC(NCH, BH);
    pass_out<<<gC, 512, smemC>>>(q, k, v, out);
}

// round 4
// speedup vs baseline: 2.2031x; 1.8844x over previous
#include <cuda_runtime.h>
#include <cuda_bf16.h>
#include <cstddef>

#define SEQ   4096
#define DIMX  128
#define BT    64
#define NCH   64
#define BHMAX 32

#define PADA  132   // row-major A / n-in-g B operands
#define PADB  136   // k-in-tg B operands

// Scratch: 128 MB state + cum/tot
__device__ float g_state[BHMAX * NCH * DIMX * DIMX];
__device__ float g_cum[BHMAX * SEQ];
__device__ float g_tot[BHMAX * NCH];

__device__ __forceinline__ unsigned f2tf(float x) {
    unsigned u;
    asm("cvt.rna.tf32.f32 %0, %1;" : "=r"(u) : "f"(x));
    return u;
}

__device__ __forceinline__ void mma8(float c[4], unsigned a0, unsigned a1,
                                     unsigned a2, unsigned a3,
                                     unsigned b0, unsigned b1) {
    asm("mma.sync.aligned.m16n8k8.row.col.f32.tf32.tf32.f32 "
        "{%0,%1,%2,%3},{%4,%5,%6,%7},{%8,%9},{%0,%1,%2,%3};"
        : "+f"(c[0]), "+f"(c[1]), "+f"(c[2]), "+f"(c[3])
        : "r"(a0), "r"(a1), "r"(a2), "r"(a3), "r"(b0), "r"(b1));
}

// ───────────── Pass A: upd_c[d][e] = Σ_j k[j][d]·dte[j]·v[j][e]  (tf32 mma) ─────────────
__global__ __launch_bounds__(256, 2)
void pass_upd(const float* __restrict__ k, const float* __restrict__ v,
              const float* __restrict__ beta)
{
    extern __shared__ unsigned smu[];
    unsigned* sk  = smu;              // [64][PADB] tf32 k[j][d]
    unsigned* sve = sk + 64 * PADB;   // [64][PADB] tf32 v[j][e]*dte[j]
    float* dte = (float*)(sve + 64 * PADB);   // [64]

    const int t = threadIdx.x, lane = t & 31, w = t >> 5;
    const int g = lane >> 2, tg = lane & 3;
    const int c = blockIdx.x, bh = blockIdx.y;
    const float* betab = beta + (size_t)bh * SEQ + c * BT;

    if (w == 0) {
        float b0 = logf(betab[lane]      + 1e-6f);
        float b1 = logf(betab[32 + lane] + 1e-6f);
        #pragma unroll
        for (int off = 1; off < 32; off <<= 1) {
            float n = __shfl_up_sync(0xffffffffu, b0, off);
            if (lane >= off) b0 += n;
        }
        float t0 = __shfl_sync(0xffffffffu, b0, 31);
        #pragma unroll
        for (int off = 1; off < 32; off <<= 1) {
            float n = __shfl_up_sync(0xffffffffu, b1, off);
            if (lane >= off) b1 += n;
        }
        float c1  = t0 + b1;
        float tot = __shfl_sync(0xffffffffu, c1, 31);
        dte[lane]      = __expf(tot - b0);
        dte[32 + lane] = __expf(tot - c1);
        g_cum[bh * SEQ + c * BT + lane]      = b0;
        g_cum[bh * SEQ + c * BT + 32 + lane] = c1;
        if (lane == 0) g_tot[bh * NCH + c] = tot;
    }
    __syncthreads();

    const float* kb = k + ((size_t)bh * SEQ + c * BT) * DIMX;
    const float* vb = v + ((size_t)bh * SEQ + c * BT) * DIMX;
    #pragma unroll
    for (int it = 0; it < 8; ++it) {
        int p = t + it * 256;
        int j = p >> 5, f = p & 31;
        float4 kk = *(const float4*)(kb + (size_t)j * DIMX + 4 * f);
        uint4 ks = {f2tf(kk.x), f2tf(kk.y), f2tf(kk.z), f2tf(kk.w)};
        *(uint4*)(sk + j * PADB + 4 * f) = ks;
        float4 vv = *(const float4*)(vb + (size_t)j * DIMX + 4 * f);
        float dd = dte[j];
        uint4 vs = {f2tf(vv.x * dd), f2tf(vv.y * dd), f2tf(vv.z * dd), f2tf(vv.w * dd)};
        *(uint4*)(sve + j * PADB + 4 * f) = vs;
    }
    __syncthreads();

    const int d0w = 32 * (w >> 1), e0w = 64 * (w & 1);
    float acc[2][8][4];
    #pragma unroll
    for (int mt = 0; mt < 2; ++mt)
        #pragma unroll
        for (int nt = 0; nt < 8; ++nt)
            #pragma unroll
            for (int r = 0; r < 4; ++r) acc[mt][nt][r] = 0.0f;

    #pragma unroll
    for (int ks = 0; ks < 8; ++ks) {
        int j0 = 8 * ks;
        unsigned a[2][4];
        #pragma unroll
        for (int mt = 0; mt < 2; ++mt) {
            int db = d0w + 16 * mt;
            a[mt][0] = sk[(j0 + tg) * PADB + db + g];
            a[mt][1] = sk[(j0 + tg) * PADB + db + 8 + g];
            a[mt][2] = sk[(j0 + tg + 4) * PADB + db + g];
            a[mt][3] = sk[(j0 + tg + 4) * PADB + db + 8 + g];
        }
        #pragma unroll
        for (int nt = 0; nt < 8; ++nt) {
            int eb = e0w + 8 * nt;
            unsigned b0 = sve[(j0 + tg) * PADB + eb + g];
            unsigned b1 = sve[(j0 + tg + 4) * PADB + eb + g];
            mma8(acc[0][nt], a[0][0], a[0][1], a[0][2], a[0][3], b0, b1);
            mma8(acc[1][nt], a[1][0], a[1][1], a[1][2], a[1][3], b0, b1);
        }
    }

    float* dst = g_state + (((size_t)(bh * NCH + c)) << 14);
    #pragma unroll
    for (int mt = 0; mt < 2; ++mt) {
        int d = d0w + 16 * mt + g;
        #pragma unroll
        for (int nt = 0; nt < 8; ++nt) {
            int e = e0w + 8 * nt + 2 * tg;
            float2 lo = {acc[mt][nt][0], acc[mt][nt][1]};
            float2 hi = {acc[mt][nt][2], acc[mt][nt][3]};
            *(float2*)(dst + d * DIMX + e)       = lo;
            *(float2*)(dst + (d + 8) * DIMX + e) = hi;
        }
    }
}

// ───────────── Pass B: in-place scan upd → S_before ─────────────
__global__ __launch_bounds__(256)
void pass_scan()
{
    __shared__ float et[NCH];
    const int t = threadIdx.x;
    const int seg = blockIdx.x, bh = blockIdx.y;
    if (t < NCH) et[t] = __expf(g_tot[bh * NCH + t]);
    __syncthreads();

    const size_t base = ((size_t)bh * NCH) << 14;
    const int off = seg * 1024 + 4 * t;
    float4 s = {0.f, 0.f, 0.f, 0.f};
    #pragma unroll 2
    for (int c = 0; c < NCH; ++c) {
        float* p = g_state + base + ((size_t)c << 14) + off;
        float4 u = *(const float4*)p;
        *(float4*)p = s;
        float e = et[c];
        s.x = s.x * e + u.x;
        s.y = s.y * e + u.y;
        s.z = s.z * e + u.z;
        s.w = s.w * e + u.w;
    }
}

// ───────────── Pass C: out = (QKᵀ⊙decay)@V + dfs⊙(Q@S_before)  (tf32 mma) ─────────────
__global__ __launch_bounds__(512, 1)
void pass_out(const float* __restrict__ q, const float* __restrict__ k,
              const float* __restrict__ v, float* __restrict__ out)
{
    extern __shared__ unsigned smu[];
    unsigned* sq  = smu;               // [64][PADA] tf32 q[i][d]
    unsigned* skA = sq + 64 * PADA;    // [64][PADA] tf32 k[j][d], then A[i][j]
    unsigned* sv  = skA + 64 * PADA;   // [64][PADB] tf32 v[j][e]
    unsigned* sS  = sv + 64 * PADB;    // [32][PADB] tf32 S block
    float* cum = (float*)(sS + 32 * PADB);  // [64]
    float* dfs = cum + 64;                  // [64]

    const int t = threadIdx.x, lane = t & 31, w = t >> 5;
    const int g = lane >> 2, tg = lane & 3;
    const int c = blockIdx.x, bh = blockIdx.y;
    const size_t cb = ((size_t)bh * SEQ + (size_t)c * BT) * DIMX;

    if (t < 64) {
        float cc = g_cum[bh * SEQ + c * BT + t];
        cum[t] = cc;
        dfs[t] = __expf(cc);
    }
    {
        const float* qrow = q + cb;
        const float* krow = k + cb;
        const float* vrow = v + cb;
        #pragma unroll
        for (int it = 0; it < 4; ++it) {
            int p = t + it * 512;
            int j = p >> 5, f = p & 31;
            float4 vq = *(const float4*)(qrow + (size_t)j * DIMX + 4 * f);
            *(uint4*)(sq + j * PADA + 4 * f) = uint4{f2tf(vq.x), f2tf(vq.y), f2tf(vq.z), f2tf(vq.w)};
            float4 vk = *(const float4*)(krow + (size_t)j * DIMX + 4 * f);
            *(uint4*)(skA + j * PADA + 4 * f) = uint4{f2tf(vk.x), f2tf(vk.y), f2tf(vk.z), f2tf(vk.w)};
            float4 vv = *(const float4*)(vrow + (size_t)j * DIMX + 4 * f);
            *(uint4*)(sv + j * PADB + 4 * f) = uint4{f2tf(vv.x), f2tf(vv.y), f2tf(vv.z), f2tf(vv.w)};
        }
    }
    __syncthreads();

    // ── QK^T (causal warp-tile skip) ──
    const int wi = w >> 2, wj = w & 3;
    const int i0 = 16 * wi, j0w = 16 * wj;
    float s[2][4];
    #pragma unroll
    for (int nt = 0; nt < 2; ++nt)
        #pragma unroll
        for (int r = 0; r < 4; ++r) s[nt][r] = 0.0f;

    if (wj <= wi) {
        #pragma unroll
        for (int ks = 0; ks < 16; ++ks) {
            int d0 = 8 * ks;
            unsigned a0 = sq[(i0 + g) * PADA + d0 + tg];
            unsigned a1 = sq[(i0 + g + 8) * PADA + d0 + tg];
            unsigned a2 = sq[(i0 + g) * PADA + d0 + tg + 4];
            unsigned a3 = sq[(i0 + g + 8) * PADA + d0 + tg + 4];
            #pragma unroll
            for (int nt = 0; nt < 2; ++nt) {
                int j0 = j0w + 8 * nt;
                unsigned b0 = skA[(j0 + g) * PADA + d0 + tg];
                unsigned b1 = skA[(j0 + g) * PADA + d0 + tg + 4];
                mma8(s[nt], a0, a1, a2, a3, b0, b1);
            }
        }
    }

    // mask + decay in registers
    float m[2][4];
    {
        int iL = i0 + g, iH = i0 + g + 8;
        float ciL = cum[iL], ciH = cum[iH];
        #pragma unroll
        for (int nt = 0; nt < 2; ++nt) {
            int jA = j0w + 8 * nt + 2 * tg, jB = jA + 1;
            float cjA = cum[jA], cjB = cum[jB];
            m[nt][0] = (jA <= iL) ? s[nt][0] * __expf(ciL - cjA) : 0.0f;
            m[nt][1] = (jB <= iL) ? s[nt][1] * __expf(ciL - cjB) : 0.0f;
            m[nt][2] = (jA <= iH) ? s[nt][2] * __expf(ciH - cjA) : 0.0f;
            m[nt][3] = (jB <= iH) ? s[nt][3] * __expf(ciH - cjB) : 0.0f;
        }
    }
    __syncthreads();   // all reads of k done — safe to overwrite with A
    #pragma unroll
    for (int nt = 0; nt < 2; ++nt) {
        int j0 = j0w + 8 * nt;
        skA[(i0 + g) * PADA + j0 + 2 * tg]         = f2tf(m[nt][0]);
        skA[(i0 + g) * PADA + j0 + 2 * tg + 1]     = f2tf(m[nt][1]);
        skA[(i0 + g + 8) * PADA + j0 + 2 * tg]     = f2tf(m[nt][2]);
        skA[(i0 + g + 8) * PADA + j0 + 2 * tg + 1] = f2tf(m[nt][3]);
    }

    // ── inter: Q @ S_before (streamed in 4 blocks of 32 d-rows) ──
    const int e0w = 32 * (w & 3);
    float o[4][4];
    #pragma unroll
    for (int nt = 0; nt < 4; ++nt)
        #pragma unroll
        for (int r = 0; r < 4; ++r) o[nt][r] = 0.0f;

    const size_t sbase = ((size_t)(bh * NCH + c)) << 14;
    for (int blk = 0; blk < 4; ++blk) {
        __syncthreads();
        #pragma unroll
        for (int it = 0; it < 2; ++it) {
            int p = t + it * 512;
            int r = p >> 5, f = p & 31;
            float4 u = *(const float4*)(g_state + sbase + (size_t)(blk * 32 + r) * DIMX + 4 * f);
            *(uint4*)(sS + r * PADB + 4 * f) = uint4{f2tf(u.x), f2tf(u.y), f2tf(u.z), f2tf(u.w)};
        }
        __syncthreads();
        #pragma unroll
        for (int ks = 0; ks < 4; ++ks) {
            int dg = blk * 32 + 8 * ks;
            int dl = 8 * ks;
            unsigned a0 = sq[(i0 + g) * PADA + dg + tg];
            unsigned a1 = sq[(i0 + g + 8) * PADA + dg + tg];
            unsigned a2 = sq[(i0 + g) * PADA + dg + tg + 4];
            unsigned a3 = sq[(i0 + g + 8) * PADA + dg + tg + 4];
            #pragma unroll
            for (int nt = 0; nt < 4; ++nt) {
                int e0 = e0w + 8 * nt;
                unsigned b0 = sS[(dl + tg) * PADB + e0 + g];
                unsigned b1 = sS[(dl + tg + 4) * PADB + e0 + g];
                mma8(o[nt], a0, a1, a2, a3, b0, b1);
            }
        }
    }
    {
        float fL = dfs[i0 + g], fH = dfs[i0 + g + 8];
        #pragma unroll
        for (int nt = 0; nt < 4; ++nt) {
            o[nt][0] *= fL; o[nt][1] *= fL;
            o[nt][2] *= fH; o[nt][3] *= fH;
        }
    }

    // ── intra: A @ V (causal k-loop truncation) ──
    const int kmax = 2 * wi + 2;
    for (int ks = 0; ks < kmax; ++ks) {
        int j0 = 8 * ks;
        unsigned a0 = skA[(i0 + g) * PADA + j0 + tg];
        unsigned a1 = skA[(i0 + g + 8) * PADA + j0 + tg];
        unsigned a2 = skA[(i0 + g) * PADA + j0 + tg + 4];
        unsigned a3 = skA[(i0 + g + 8) * PADA + j0 + tg + 4];
        #pragma unroll
        for (int nt = 0; nt < 4; ++nt) {
            int e0 = e0w + 8 * nt;
            unsigned b0 = sv[(j0 + tg) * PADB + e0 + g];
            unsigned b1 = sv[(j0 + tg + 4) * PADB + e0 + g];
            mma8(o[nt], a0, a1, a2, a3, b0, b1);
        }
    }

    float* dst = out + cb;
    #pragma unroll
    for (int nt = 0; nt < 4; ++nt) {
        int e = e0w + 8 * nt + 2 * tg;
        int i = i0 + g;
        float2 lo = {o[nt][0], o[nt][1]};
        float2 hi = {o[nt][2], o[nt][3]};
        *(float2*)(dst + (size_t)i * DIMX + e)       = lo;
        *(float2*)(dst + (size_t)(i + 8) * DIMX + e) = hi;
    }
}

extern "C" void kernel_launch(void* const* d_in, const int* in_sizes, int n_in,
                              void* d_out, int out_size)
{
    const float* q    = (const float*)d_in[0];
    const float* k    = (const float*)d_in[1];
    const float* v    = (const float*)d_in[2];
    const float* beta = (const float*)d_in[3];
    float* out = (float*)d_out;

    const int BH = in_sizes[3] / SEQ;   // 32

    const size_t smemA = (size_t)(64 * PADB * 2) * 4 + 64 * 4 + 64;
    const size_t smemC = (size_t)(64 * PADA * 2 + 64 * PADB + 32 * PADB) * 4 + 128 * 4 + 64;
    cudaFuncSetAttribute(pass_upd, cudaFuncAttributeMaxDynamicSharedMemorySize, (int)smemA);
    cudaFuncSetAttribute(pass_out, cudaFuncAttributeMaxDynamicSharedMemorySize, (int)smemC);

    dim3 gA(NCH, BH);
    pass_upd<<<gA, 256, smemA>>>(k, v, beta);

    dim3 gB(16, BH);
    pass_scan<<<gB, 256>>>();

    dim3 gC(NCH, BH);
    pass_out<<<gC, 512, smemC>>>(q, k, v, out);
}

// round 5
// speedup vs baseline: 2.2678x; 1.0294x over previous
#include <cuda_runtime.h>
#include <cuda_bf16.h>
#include <cstddef>

#define SEQ   4096
#define DIMX  128
#define BT    64
#define NCH   64
#define BHMAX 32

#define PADA  132   // ≡4 (mod 32): row-indexed-by-g operands conflict-free
#define PADB  136   // ≡8 (mod 32): k-indexed-by-tg operands conflict-free

__device__ float g_state[BHMAX * NCH * DIMX * DIMX];
__device__ float g_cum[BHMAX * SEQ];
__device__ float g_tot[BHMAX * NCH];

__device__ __forceinline__ unsigned f2tf(float x) {
    unsigned u;
    asm("cvt.rna.tf32.f32 %0, %1;" : "=r"(u) : "f"(x));
    return u;
}

__device__ __forceinline__ void mma8(float c[4], unsigned a0, unsigned a1,
                                     unsigned a2, unsigned a3,
                                     unsigned b0, unsigned b1) {
    asm("mma.sync.aligned.m16n8k8.row.col.f32.tf32.tf32.f32 "
        "{%0,%1,%2,%3},{%4,%5,%6,%7},{%8,%9},{%0,%1,%2,%3};"
        : "+f"(c[0]), "+f"(c[1]), "+f"(c[2]), "+f"(c[3])
        : "r"(a0), "r"(a1), "r"(a2), "r"(a3), "r"(b0), "r"(b1));
}

// ───────────── Pass A: upd_c[d][e] = Σ_j k[j][d]·dte[j]·v[j][e]  (tf32 mma) ─────────────
__global__ __launch_bounds__(256, 2)
void pass_upd(const float* __restrict__ k, const float* __restrict__ v,
              const float* __restrict__ beta)
{
    extern __shared__ unsigned smu[];
    unsigned* sk  = smu;              // [64][PADB]
    unsigned* sve = sk + 64 * PADB;   // [64][PADB]
    float* dte = (float*)(sve + 64 * PADB);

    const int t = threadIdx.x, lane = t & 31, w = t >> 5;
    const int g = lane >> 2, tg = lane & 3;
    const int c = blockIdx.x, bh = blockIdx.y;
    const float* betab = beta + (size_t)bh * SEQ + c * BT;

    if (w == 0) {
        float b0 = logf(betab[lane]      + 1e-6f);
        float b1 = logf(betab[32 + lane] + 1e-6f);
        #pragma unroll
        for (int off = 1; off < 32; off <<= 1) {
            float n = __shfl_up_sync(0xffffffffu, b0, off);
            if (lane >= off) b0 += n;
        }
        float t0 = __shfl_sync(0xffffffffu, b0, 31);
        #pragma unroll
        for (int off = 1; off < 32; off <<= 1) {
            float n = __shfl_up_sync(0xffffffffu, b1, off);
            if (lane >= off) b1 += n;
        }
        float c1  = t0 + b1;
        float tot = __shfl_sync(0xffffffffu, c1, 31);
        dte[lane]      = __expf(tot - b0);
        dte[32 + lane] = __expf(tot - c1);
        g_cum[bh * SEQ + c * BT + lane]      = b0;
        g_cum[bh * SEQ + c * BT + 32 + lane] = c1;
        if (lane == 0) g_tot[bh * NCH + c] = tot;
    }
    __syncthreads();

    const float* kb = k + ((size_t)bh * SEQ + c * BT) * DIMX;
    const float* vb = v + ((size_t)bh * SEQ + c * BT) * DIMX;
    #pragma unroll
    for (int it = 0; it < 8; ++it) {
        int p = t + it * 256;
        int j = p >> 5, f = p & 31;
        float4 kk = *(const float4*)(kb + (size_t)j * DIMX + 4 * f);
        *(uint4*)(sk + j * PADB + 4 * f) = uint4{f2tf(kk.x), f2tf(kk.y), f2tf(kk.z), f2tf(kk.w)};
        float4 vv = *(const float4*)(vb + (size_t)j * DIMX + 4 * f);
        float dd = dte[j];
        *(uint4*)(sve + j * PADB + 4 * f) =
            uint4{f2tf(vv.x * dd), f2tf(vv.y * dd), f2tf(vv.z * dd), f2tf(vv.w * dd)};
    }
    __syncthreads();

    const int d0w = 32 * (w >> 1), e0w = 64 * (w & 1);
    float acc[2][8][4];
    #pragma unroll
    for (int mt = 0; mt < 2; ++mt)
        #pragma unroll
        for (int nt = 0; nt < 8; ++nt)
            #pragma unroll
            for (int r = 0; r < 4; ++r) acc[mt][nt][r] = 0.0f;

    #pragma unroll
    for (int ks = 0; ks < 8; ++ks) {
        int j0 = 8 * ks;
        unsigned a[2][4];
        #pragma unroll
        for (int mt = 0; mt < 2; ++mt) {
            int db = d0w + 16 * mt;
            a[mt][0] = sk[(j0 + tg) * PADB + db + g];
            a[mt][1] = sk[(j0 + tg) * PADB + db + 8 + g];
            a[mt][2] = sk[(j0 + tg + 4) * PADB + db + g];
            a[mt][3] = sk[(j0 + tg + 4) * PADB + db + 8 + g];
        }
        #pragma unroll
        for (int nt = 0; nt < 8; ++nt) {
            int eb = e0w + 8 * nt;
            unsigned b0 = sve[(j0 + tg) * PADB + eb + g];
            unsigned b1 = sve[(j0 + tg + 4) * PADB + eb + g];
            mma8(acc[0][nt], a[0][0], a[0][1], a[0][2], a[0][3], b0, b1);
            mma8(acc[1][nt], a[1][0], a[1][1], a[1][2], a[1][3], b0, b1);
        }
    }

    float* dst = g_state + (((size_t)(bh * NCH + c)) << 14);
    #pragma unroll
    for (int mt = 0; mt < 2; ++mt) {
        int d = d0w + 16 * mt + g;
        #pragma unroll
        for (int nt = 0; nt < 8; ++nt) {
            int e = e0w + 8 * nt + 2 * tg;
            *(float2*)(dst + d * DIMX + e)       = float2{acc[mt][nt][0], acc[mt][nt][1]};
            *(float2*)(dst + (d + 8) * DIMX + e) = float2{acc[mt][nt][2], acc[mt][nt][3]};
        }
    }
}

// ───────────── Pass B: in-place scan upd → S_before ─────────────
__global__ __launch_bounds__(256)
void pass_scan()
{
    __shared__ float et[NCH];
    const int t = threadIdx.x;
    const int seg = blockIdx.x, bh = blockIdx.y;
    if (t < NCH) et[t] = __expf(g_tot[bh * NCH + t]);
    __syncthreads();

    const size_t base = ((size_t)bh * NCH) << 14;
    const int off = seg * 1024 + 4 * t;
    float4 s = {0.f, 0.f, 0.f, 0.f};
    #pragma unroll 2
    for (int c = 0; c < NCH; ++c) {
        float* p = g_state + base + ((size_t)c << 14) + off;
        float4 u = *(const float4*)p;
        *(float4*)p = s;
        float e = et[c];
        s.x = s.x * e + u.x;
        s.y = s.y * e + u.y;
        s.z = s.z * e + u.z;
        s.w = s.w * e + u.w;
    }
}

// ───────────── Pass C: out = (QKᵀ⊙decay)@V + dfs⊙(Q@S_before) ─────────────
// 256 threads, 8 warps: warp = (wi = w>>1 → 16-row i-tile, half = w&1).
// QKᵀ: half selects j-half (32 cols). Output/inter/intra: half selects e-half (64 cols).
__global__ __launch_bounds__(256, 1)
void pass_out(const float* __restrict__ q, const float* __restrict__ k,
              const float* __restrict__ v, float* __restrict__ out)
{
    extern __shared__ unsigned smu[];
    unsigned* sq  = smu;               // [64][PADA] tf32 q; overlaid by sS [32][PADB] later
    unsigned* skA = sq + 64 * PADA;    // [64][PADA] tf32 k, then A
    unsigned* sv  = skA + 64 * PADA;   // [64][PADB] tf32 v
    unsigned* sS  = sq;                // overlay (sq dead after fragment extraction)
    float* cum = (float*)(sv + 64 * PADB);  // [64]
    float* dfs = cum + 64;                  // [64]

    const int t = threadIdx.x, lane = t & 31, w = t >> 5;
    const int g = lane >> 2, tg = lane & 3;
    const int wi = w >> 1, half = w & 1;
    const int i0 = 16 * wi;
    const int c = blockIdx.x, bh = blockIdx.y;
    const size_t cb = ((size_t)bh * SEQ + (size_t)c * BT) * DIMX;

    if (t < 64) {
        float cc = g_cum[bh * SEQ + c * BT + t];
        cum[t] = cc;
        dfs[t] = __expf(cc);
    }
    {
        const float* qrow = q + cb;
        const float* krow = k + cb;
        const float* vrow = v + cb;
        #pragma unroll
        for (int it = 0; it < 8; ++it) {
            int p = t + it * 256;
            int j = p >> 5, f = p & 31;
            float4 vq = *(const float4*)(qrow + (size_t)j * DIMX + 4 * f);
            *(uint4*)(sq + j * PADA + 4 * f) = uint4{f2tf(vq.x), f2tf(vq.y), f2tf(vq.z), f2tf(vq.w)};
            float4 vk = *(const float4*)(krow + (size_t)j * DIMX + 4 * f);
            *(uint4*)(skA + j * PADA + 4 * f) = uint4{f2tf(vk.x), f2tf(vk.y), f2tf(vk.z), f2tf(vk.w)};
            float4 vv = *(const float4*)(vrow + (size_t)j * DIMX + 4 * f);
            *(uint4*)(sv + j * PADB + 4 * f) = uint4{f2tf(vv.x), f2tf(vv.y), f2tf(vv.z), f2tf(vv.w)};
        }
    }
    __syncthreads();

    // ── extract Q fragments once (reused by QKᵀ and Q@S) ──
    unsigned qa[16][4];
    #pragma unroll
    for (int kk = 0; kk < 16; ++kk) {
        int d0 = 8 * kk;
        qa[kk][0] = sq[(i0 + g) * PADA + d0 + tg];
        qa[kk][1] = sq[(i0 + g + 8) * PADA + d0 + tg];
        qa[kk][2] = sq[(i0 + g) * PADA + d0 + tg + 4];
        qa[kk][3] = sq[(i0 + g + 8) * PADA + d0 + tg + 4];
    }

    // ── QKᵀ with causal nt-tile skip ──
    const int j0w = 32 * half;
    float s[4][4];
    #pragma unroll
    for (int nt = 0; nt < 4; ++nt)
        #pragma unroll
        for (int r = 0; r < 4; ++r) s[nt][r] = 0.0f;

    #pragma unroll
    for (int nt = 0; nt < 4; ++nt) {
        int j0 = j0w + 8 * nt;
        if (j0 <= i0 + 15) {
            #pragma unroll
            for (int kk = 0; kk < 16; ++kk) {
                int d0 = 8 * kk;
                unsigned b0 = skA[(j0 + g) * PADA + d0 + tg];
                unsigned b1 = skA[(j0 + g) * PADA + d0 + tg + 4];
                mma8(s[nt], qa[kk][0], qa[kk][1], qa[kk][2], qa[kk][3], b0, b1);
            }
        }
    }

    // mask + decay in registers
    float m[4][4];
    {
        int iL = i0 + g, iH = i0 + g + 8;
        float ciL = cum[iL], ciH = cum[iH];
        #pragma unroll
        for (int nt = 0; nt < 4; ++nt) {
            int jA = j0w + 8 * nt + 2 * tg, jB = jA + 1;
            float cjA = cum[jA], cjB = cum[jB];
            m[nt][0] = (jA <= iL) ? s[nt][0] * __expf(ciL - cjA) : 0.0f;
            m[nt][1] = (jB <= iL) ? s[nt][1] * __expf(ciL - cjB) : 0.0f;
            m[nt][2] = (jA <= iH) ? s[nt][2] * __expf(ciH - cjA) : 0.0f;
            m[nt][3] = (jB <= iH) ? s[nt][3] * __expf(ciH - cjB) : 0.0f;
        }
    }
    __syncthreads();   // all k reads + sq fragment reads complete

    #pragma unroll
    for (int nt = 0; nt < 4; ++nt) {
        int j0 = j0w + 8 * nt;
        if (j0 <= i0 + 15) {
            skA[(i0 + g) * PADA + j0 + 2 * tg]         = f2tf(m[nt][0]);
            skA[(i0 + g) * PADA + j0 + 2 * tg + 1]     = f2tf(m[nt][1]);
            skA[(i0 + g + 8) * PADA + j0 + 2 * tg]     = f2tf(m[nt][2]);
            skA[(i0 + g + 8) * PADA + j0 + 2 * tg + 1] = f2tf(m[nt][3]);
        }
    }

    // ── inter: Q @ S_before (sS overlaid on sq, 4 blocks of 32 d-rows) ──
    const int e0w = 64 * half;
    float o[8][4];
    #pragma unroll
    for (int nt = 0; nt < 8; ++nt)
        #pragma unroll
        for (int r = 0; r < 4; ++r) o[nt][r] = 0.0f;

    const size_t sbase = ((size_t)(bh * NCH + c)) << 14;
    #pragma unroll
    for (int blk = 0; blk < 4; ++blk) {
        __syncthreads();
        #pragma unroll
        for (int it = 0; it < 4; ++it) {
            int p = t + it * 256;
            int r = p >> 5, f = p & 31;
            float4 u = *(const float4*)(g_state + sbase + (size_t)(blk * 32 + r) * DIMX + 4 * f);
            *(uint4*)(sS + r * PADB + 4 * f) = uint4{f2tf(u.x), f2tf(u.y), f2tf(u.z), f2tf(u.w)};
        }
        __syncthreads();
        #pragma unroll
        for (int ks = 0; ks < 4; ++ks) {
            int dl = 8 * ks;
            const int kk = blk * 4 + ks;
            #pragma unroll
            for (int nt = 0; nt < 8; ++nt) {
                int e0 = e0w + 8 * nt;
                unsigned b0 = sS[(dl + tg) * PADB + e0 + g];
                unsigned b1 = sS[(dl + tg + 4) * PADB + e0 + g];
                mma8(o[nt], qa[kk][0], qa[kk][1], qa[kk][2], qa[kk][3], b0, b1);
            }
        }
    }
    {
        float fL = dfs[i0 + g], fH = dfs[i0 + g + 8];
        #pragma unroll
        for (int nt = 0; nt < 8; ++nt) {
            o[nt][0] *= fL; o[nt][1] *= fL;
            o[nt][2] *= fH; o[nt][3] *= fH;
        }
    }

    // ── intra: A @ V with causal ks truncation ──
    const int kmax = 2 * wi + 2;
    for (int ks = 0; ks < kmax; ++ks) {
        int j0 = 8 * ks;
        unsigned a0 = skA[(i0 + g) * PADA + j0 + tg];
        unsigned a1 = skA[(i0 + g + 8) * PADA + j0 + tg];
        unsigned a2 = skA[(i0 + g) * PADA + j0 + tg + 4];
        unsigned a3 = skA[(i0 + g + 8) * PADA + j0 + tg + 4];
        #pragma unroll
        for (int nt = 0; nt < 8; ++nt) {
            int e0 = e0w + 8 * nt;
            unsigned b0 = sv[(j0 + tg) * PADB + e0 + g];
            unsigned b1 = sv[(j0 + tg + 4) * PADB + e0 + g];
            mma8(o[nt], a0, a1, a2, a3, b0, b1);
        }
    }

    float* dst = out + cb;
    #pragma unroll
    for (int nt = 0; nt < 8; ++nt) {
        int e = e0w + 8 * nt + 2 * tg;
        int i = i0 + g;
        *(float2*)(dst + (size_t)i * DIMX + e)       = float2{o[nt][0], o[nt][1]};
        *(float2*)(dst + (size_t)(i + 8) * DIMX + e) = float2{o[nt][2], o[nt][3]};
    }
}

extern "C" void kernel_launch(void* const* d_in, const int* in_sizes, int n_in,
                              void* d_out, int out_size)
{
    const float* q    = (const float*)d_in[0];
    const float* k    = (const float*)d_in[1];
    const float* v    = (const float*)d_in[2];
    const float* beta = (const float*)d_in[3];
    float* out = (float*)d_out;

    const int BH = in_sizes[3] / SEQ;   // 32

    const size_t smemA = (size_t)(64 * PADB * 2) * 4 + 64 * 4 + 64;
    const size_t smemC = (size_t)(64 * PADA * 2 + 64 * PADB) * 4 + 128 * 4 + 64;
    cudaFuncSetAttribute(pass_upd, cudaFuncAttributeMaxDynamicSharedMemorySize, (int)smemA);
    cudaFuncSetAttribute(pass_out, cudaFuncAttributeMaxDynamicSharedMemorySize, (int)smemC);

    dim3 gA(NCH, BH);
    pass_upd<<<gA, 256, smemA>>>(k, v, beta);

    dim3 gB(16, BH);
    pass_scan<<<gB, 256>>>();

    dim3 gC(NCH, BH);
    pass_out<<<gC, 256, smemC>>>(q, k, v, out);
}